// round 6
// baseline (speedup 1.0000x reference)
#include <cuda_runtime.h>
#include <stdint.h>

// GreedyInvasionMemory: sequential scan, 2048 steps over 128-dim q/k/v.
// Single persistent CTA, 1024 threads. J in registers, Pqq/Pqv in smem.
// Incremental trace maintenance (double) replaces per-step O(d^3) traces.

#define T_STEPS 2048
#define D 128
#define NTHREADS 1024
#define NWARPS 32

struct Smem {
    float Pqq[D * D];          // sum of q q^T   (64 KB)
    float Pqv[D * D];          // sum of q v^T   (64 KB)  [d_k, d_v]
    float vecs[2][3][D];       // double-buffered q/k/v rows (3 KB)
    float u[D];                // Pqq @ k
    float slots_sl[NWARPS];
    float slots_ku[NWARPS];
    float slots_jqv[NWARPS];
    float slots_jq2[NWARPS];
    float slots_mu[NWARPS];
    float vvs;                 // v . v
    float abf[2];              // broadcast (a, b) for deferred J update
};

__device__ __forceinline__ float wred(float x) {
    x += __shfl_xor_sync(0xffffffffu, x, 16);
    x += __shfl_xor_sync(0xffffffffu, x, 8);
    x += __shfl_xor_sync(0xffffffffu, x, 4);
    x += __shfl_xor_sync(0xffffffffu, x, 2);
    x += __shfl_xor_sync(0xffffffffu, x, 1);
    return x;
}

__device__ __forceinline__ float dot4(float4 a, float4 b) {
    return a.x * b.x + a.y * b.y + a.z * b.z + a.w * b.w;
}

extern __shared__ char smem_raw[];

__global__ void __launch_bounds__(NTHREADS, 1)
gim_kernel(const float* __restrict__ qg,
           const float* __restrict__ kg,
           const float* __restrict__ vg,
           float* __restrict__ out)
{
    Smem& S = *reinterpret_cast<Smem*>(smem_raw);
    const int tid = threadIdx.x;
    const int w = tid >> 5;      // warp id: owns rows w, w+32, w+64, w+96
    const int L = tid & 31;      // lane: columns 4L..4L+3

    // ---- init ----
    for (int i = tid; i < D * D; i += NTHREADS) { S.Pqq[i] = 0.f; S.Pqv[i] = 0.f; }
    if (tid < 3 * D) {
        const int a = tid / D, i = tid % D;
        const float* src = (a == 0) ? qg : ((a == 1) ? kg : vg);
        S.vecs[0][a][i] = src[i];   // step 0 data
        S.vecs[1][a][i] = 0.f;      // "previous" step data (unused, b=0)
    }
    if (tid == 0) { S.abf[0] = 1.f; S.abf[1] = 0.f; }

    float4 Jreg[4];
#pragma unroll
    for (int j = 0; j < 4; j++) Jreg[j] = make_float4(0.f, 0.f, 0.f, 0.f);

    // long-horizon accumulators (only thread 0's values matter)
    double T1 = 0.0, T2 = 0.0, Tvv = 0.0;

    __syncthreads();

    for (int t = 0; t < T_STEPS; ++t) {
        const int cur = t & 1, nxt = cur ^ 1;

        // prefetch next step's q/k/v into registers (hide L2/DRAM latency)
        float pref = 0.f; int pa = 0, pi = 0;
        if (tid < 3 * D && (t + 1) < T_STEPS) {
            pa = tid / D; pi = tid % D;
            const float* src = (pa == 0) ? qg : ((pa == 1) ? kg : vg);
            pref = src[(t + 1) * D + pi];
        }

        const float aco = S.abf[0];   // deferred J-update coeffs from step t-1
        const float bco = S.abf[1];

        const float* Qs  = S.vecs[cur][0];
        const float* Ks  = S.vecs[cur][1];
        const float* Vs  = S.vecs[cur][2];
        const float* VPs = S.vecs[nxt][2];  // v_{t-1}

        const float4 q4  = reinterpret_cast<const float4*>(Qs)[L];
        const float4 k4  = reinterpret_cast<const float4*>(Ks)[L];
        const float4 v4  = reinterpret_cast<const float4*>(Vs)[L];
        const float4 kp4 = reinterpret_cast<const float4*>(S.vecs[nxt][1])[L]; // k_{t-1}

        // ---- phase 1: P updates (fused with dots), deferred J update + Jq ----
        float slp = 0.f, kup = 0.f, jqvp = 0.f, jq2acc = 0.f;
#pragma unroll
        for (int j = 0; j < 4; j++) {
            const int r = w + 32 * j;
            const float qr = Qs[r], kr = Ks[r], vr = Vs[r], vpr = VPs[r];

            // Pqq row r: RMW + u partial (u = Pqq_t @ k) + ku fold
            float4* pqp = reinterpret_cast<float4*>(S.Pqq) + r * 32 + L;
            float4 pq = *pqp;
            pq.x = fmaf(qr, q4.x, pq.x); pq.y = fmaf(qr, q4.y, pq.y);
            pq.z = fmaf(qr, q4.z, pq.z); pq.w = fmaf(qr, q4.w, pq.w);
            *pqp = pq;
            const float up = dot4(pq, k4);
            kup = fmaf(kr, up, kup);                  // ku = k^T Pqq_t k (folded)

            // Pqv row r: RMW + s_l fold (s_l_sum = k^T Pqv_t v)
            float4* pvp = reinterpret_cast<float4*>(S.Pqv) + r * 32 + L;
            float4 pv = *pvp;
            pv.x = fmaf(qr, v4.x, pv.x); pv.y = fmaf(qr, v4.y, pv.y);
            pv.z = fmaf(qr, v4.z, pv.z); pv.w = fmaf(qr, v4.w, pv.w);
            *pvp = pv;
            const float wp = dot4(pv, v4);
            slp = fmaf(kr, wp, slp);

            // J row r: apply deferred update J <- a*J + b * v_{t-1}[r] * k_{t-1},
            // then Jq = J_{t-1} @ q_t
            const float bv = bco * vpr;
            float4 Jn;
            Jn.x = fmaf(aco, Jreg[j].x, bv * kp4.x);
            Jn.y = fmaf(aco, Jreg[j].y, bv * kp4.y);
            Jn.z = fmaf(aco, Jreg[j].z, bv * kp4.z);
            Jn.w = fmaf(aco, Jreg[j].w, bv * kp4.w);
            Jreg[j] = Jn;
            const float jq = dot4(Jn, q4);
            jqvp = fmaf(vr, jq, jqvp);                // v . (J q)  (folded)

            const float ur  = wred(up);               // u[r]
            const float jqr = wred(jq);               // (Jq)[r]
            if (L == 0) {
                S.u[r] = ur;
                jq2acc = fmaf(jqr, jqr, jq2acc);      // || J q ||^2 partial
            }
        }
        slp = wred(slp); kup = wred(kup); jqvp = wred(jqvp);
        if (L == 0) {
            S.slots_sl[w] = slp; S.slots_ku[w] = kup;
            S.slots_jqv[w] = jqvp; S.slots_jq2[w] = jq2acc;
        }
        if (w == 0) {
            float vvp = wred(dot4(v4, v4));
            if (L == 0) S.vvs = vvp;
        }
        __syncthreads();   // u[] + slots ready; vecs[nxt] reads done

        // store prefetched next-step vectors into the freed buffer
        if (tid < 3 * D && (t + 1) < T_STEPS) S.vecs[nxt][pa][pi] = pref;

        // ---- phase 2: mu = v^T J_{t-1} (Pqq_t k) ----
        {
            const float4 u4 = reinterpret_cast<const float4*>(S.u)[L];
            float mup = 0.f;
#pragma unroll
            for (int j = 0; j < 4; j++) {
                const int r = w + 32 * j;
                mup = fmaf(Vs[r], dot4(Jreg[j], u4), mup);
            }
            mup = wred(mup);
            if (L == 0) S.slots_mu[w] = mup;
        }
        __syncthreads();

        // ---- scalar phase (warp 0) ----
        if (w == 0) {
            const float sl  = wred(S.slots_sl[L]);
            const float ku  = wred(S.slots_ku[L]);
            const float jqv = wred(S.slots_jqv[L]);
            const float jq2 = wred(S.slots_jq2[L]);
            const float mu  = wred(S.slots_mu[L]);
            if (L == 0) {
                const float vv = S.vvs;
                const double T1p = T1 + (double)jqv;   // trace(J_{t-1} Pqv_t)
                const double T2p = T2 + (double)jq2;   // trace(J_{t-1} Pqq_t J^T)
                Tvv += (double)vv;

                const float fl  = (float)(t + 1);
                const float sJ  = (float)T1p / fl;
                const float AJJ = (float)T2p / fl;
                const float sl_ = sl / fl;
                const float All = vv * ku / fl;
                const float AJl = mu / fl;
                const bool first = (t == 0);

                const float AJJs = (first || AJJ == 0.f) ? 1.f : AJJ;
                const float Alls = (first || All == 0.f) ? 1.f : All;
                const float denom = AJJ * All - AJl * AJl;
                const float denoms = (first || denom == 0.f) ? 1.f : denom;

                const float margin = sl_ - AJl * (sJ / AJJs);
                const float wf = (All * sJ - AJl * sl_) / denoms;
                const float wi = (AJJ * sl_ - AJl * sJ) / denoms;
                const float wfc = (wi <= 0.f) ? (sJ / AJJs) : ((wf <= 0.f) ? 0.f : wf);
                const float wic = (wi <= 0.f) ? 0.f : ((wf <= 0.f) ? (sl_ / Alls) : wi);
                const bool dou = margin > 0.f;

                const float A = first ? 0.f : (dou ? wfc : 1.f);
                const float B = first ? 1.f : (dou ? wic : 0.f);

                // post-update traces (sum scale)
                T1 = (double)A * T1p + (double)B * (double)sl;
                T2 = (double)A * (double)A * T2p
                   + 2.0 * (double)A * (double)B * (double)mu
                   + (double)B * (double)B * (double)ku * (double)vv;

                const double dl = (double)(t + 1);
                out[t]           = (float)((0.5 * Tvv - T1 + 0.5 * T2) / dl);
                out[T_STEPS + t] = (first || dou) ? 1.f : 0.f;

                S.abf[0] = A; S.abf[1] = B;   // deferred to next step's phase 1
            }
        }
        __syncthreads();
    }

    // ---- apply final deferred J update, write J ----
    {
        const float aco = S.abf[0];
        const float bco = S.abf[1];
        const int cur = (T_STEPS - 1) & 1;   // buffer holding step 2047 data
        const float4 kc4 = reinterpret_cast<const float4*>(S.vecs[cur][1])[L];
        const float* Vc = S.vecs[cur][2];
        float4* Jout = reinterpret_cast<float4*>(out + 2 * T_STEPS);
#pragma unroll
        for (int j = 0; j < 4; j++) {
            const int r = w + 32 * j;
            const float bv = bco * Vc[r];
            float4 Jn;
            Jn.x = fmaf(aco, Jreg[j].x, bv * kc4.x);
            Jn.y = fmaf(aco, Jreg[j].y, bv * kc4.y);
            Jn.z = fmaf(aco, Jreg[j].z, bv * kc4.z);
            Jn.w = fmaf(aco, Jreg[j].w, bv * kc4.w);
            Jout[r * 32 + L] = Jn;
        }
    }
}

extern "C" void kernel_launch(void* const* d_in, const int* in_sizes, int n_in,
                              void* d_out, int out_size)
{
    const float* q = (const float*)d_in[0];
    const float* k = (const float*)d_in[1];
    const float* v = (const float*)d_in[2];
    float* out = (float*)d_out;

    (void)in_sizes; (void)n_in; (void)out_size;

    cudaFuncSetAttribute(gim_kernel,
                         cudaFuncAttributeMaxDynamicSharedMemorySize,
                         (int)sizeof(Smem));
    gim_kernel<<<1, NTHREADS, sizeof(Smem)>>>(q, k, v, out);
}

// round 7
// speedup vs baseline: 1.6227x; 1.6227x over previous
#include <cuda_runtime.h>
#include <stdint.h>

// GreedyInvasionMemory v2: 512 threads, 16 warps, warp owns rows {w+16j}.
// J and Pqv in registers; Pqq in smem (RMW once/step). u via Pqq symmetry
// (column partials, no per-row shuffles). Scalar phase of step t-1 overlaps
// the P-RMW phase of step t. 3 barriers/step.

#define T_STEPS 2048
#define D 128
#define NT 512
#define NW 16
#define WSTRIDE 133   // padded stride for wpart (5L+r bank pattern, conflict-free)

struct Smem {
    float Pqq[D * D];            // 64 KB  sum q q^T
    float vecs[2][3][D];         // double-buffered q/k/v
    float upart[NW * D];         // per-warp column partials of u' = Pqq_{t-1} k
    float wpart[32 * WSTRIDE];   // per-lane partials of w = J q  (padded)
    float u[D];                  // reduced u'
    float slot_sl[2][NW];        // parity double-buffered (raced by SC overlap)
    float slot_jqv[NW];
    float slot_mu[NW];
    float slot_ku[4];
    float slot_jq2[4];
    float qk_s, vv_s;
    float abf[2];                // (A, B) for deferred J update
};

__device__ __forceinline__ float wred(float x) {
    x += __shfl_xor_sync(0xffffffffu, x, 16);
    x += __shfl_xor_sync(0xffffffffu, x, 8);
    x += __shfl_xor_sync(0xffffffffu, x, 4);
    x += __shfl_xor_sync(0xffffffffu, x, 2);
    x += __shfl_xor_sync(0xffffffffu, x, 1);
    return x;
}

__device__ __forceinline__ float dot4(float4 a, float4 b) {
    return a.x * b.x + a.y * b.y + a.z * b.z + a.w * b.w;
}

// Scalar phase for step t. Executed by warp 0 only (all 32 lanes for wreds).
__device__ __forceinline__ void scalar_phase(Smem& S, int t, int L,
                                             double& T1, double& T2, double& Tvv,
                                             float* __restrict__ out)
{
    const int par = t & 1;
    float a1 = (L < NW) ? S.slot_sl[par][L] : 0.f;
    float a2 = (L < NW) ? S.slot_jqv[L]     : 0.f;
    float a3 = (L < NW) ? S.slot_mu[L]      : 0.f;
    const float sl  = wred(a1);
    const float jqv = wred(a2);
    const float mup = wred(a3);
    if (L == 0) {
        const float ku0 = S.slot_ku[0] + S.slot_ku[1] + S.slot_ku[2] + S.slot_ku[3];
        const float jq2 = S.slot_jq2[0] + S.slot_jq2[1] + S.slot_jq2[2] + S.slot_jq2[3];
        const float qk = S.qk_s;
        const float vv = S.vv_s;
        const float ku = fmaf(qk, qk, ku0);     // k^T Pqq_t k
        const float mu = fmaf(jqv, qk, mup);    // v^T J Pqq_t k

        const double T1p = T1 + (double)jqv;    // trace(J Pqv_t), sum scale
        const double T2p = T2 + (double)jq2;    // trace(J Pqq_t J^T), sum scale
        Tvv += (double)vv;

        const float fl  = (float)(t + 1);
        const float inv = 1.f / fl;
        const float sJ  = (float)T1p * inv;
        const float AJJ = (float)T2p * inv;
        const float sl_ = sl * inv;
        const float All = vv * ku * inv;
        const float AJl = mu * inv;
        const bool first = (t == 0);

        const float AJJs = (first || AJJ == 0.f) ? 1.f : AJJ;
        const float Alls = (first || All == 0.f) ? 1.f : All;
        const float denom = AJJ * All - AJl * AJl;
        const float denoms = (first || denom == 0.f) ? 1.f : denom;

        const float margin = sl_ - AJl * (sJ / AJJs);
        const float wf = (All * sJ - AJl * sl_) / denoms;
        const float wi = (AJJ * sl_ - AJl * sJ) / denoms;
        const float wfc = (wi <= 0.f) ? (sJ / AJJs) : ((wf <= 0.f) ? 0.f : wf);
        const float wic = (wi <= 0.f) ? 0.f : ((wf <= 0.f) ? (sl_ / Alls) : wi);
        const bool dou = margin > 0.f;

        const float A = first ? 0.f : (dou ? wfc : 1.f);
        const float B = first ? 1.f : (dou ? wic : 0.f);

        T1 = (double)A * T1p + (double)B * (double)sl;
        T2 = (double)A * (double)A * T2p
           + 2.0 * (double)A * (double)B * (double)mu
           + (double)B * (double)B * (double)ku * (double)vv;

        out[t]           = (float)(0.5 * Tvv - T1 + 0.5 * T2) * inv;
        out[T_STEPS + t] = (first || dou) ? 1.f : 0.f;

        S.abf[0] = A; S.abf[1] = B;
    }
}

extern __shared__ char smem_raw[];

__global__ void __launch_bounds__(NT, 1)
gim_kernel(const float* __restrict__ qg,
           const float* __restrict__ kg,
           const float* __restrict__ vg,
           float* __restrict__ out)
{
    Smem& S = *reinterpret_cast<Smem*>(smem_raw);
    const int tid = threadIdx.x;
    const int w = tid >> 5;     // warp 0..15, owns rows w+16j
    const int L = tid & 31;     // lane: cols 4L..4L+3

    for (int i = tid; i < D * D; i += NT) S.Pqq[i] = 0.f;
    if (tid < 3 * D) {
        const int a = tid / D, i = tid % D;
        const float* src = (a == 0) ? qg : ((a == 1) ? kg : vg);
        S.vecs[0][a][i] = src[i];
        S.vecs[1][a][i] = 0.f;
    }
    if (tid == 0) { S.abf[0] = 1.f; S.abf[1] = 0.f; }

    float4 J[8], Pv[8];
#pragma unroll
    for (int j = 0; j < 8; j++) {
        J[j]  = make_float4(0.f, 0.f, 0.f, 0.f);
        Pv[j] = make_float4(0.f, 0.f, 0.f, 0.f);
    }
    double T1 = 0.0, T2 = 0.0, Tvv = 0.0;

    __syncthreads();

    for (int t = 0; t < T_STEPS; ++t) {
        const int cur = t & 1, nxt = cur ^ 1;

        // ---- scalar phase for step t-1 (warp 0) overlapped with P-phase ----
        if (t > 0 && w == 0) scalar_phase(S, t - 1, L, T1, T2, Tvv, out);

        // prefetch next step's vectors (threads 128..511)
        float pref = 0.f; int pa = 0, pi = 0;
        const bool doPref = (tid >= 128) && (t + 1 < T_STEPS);
        if (doPref) {
            const int idx = tid - 128;
            pa = idx >> 7; pi = idx & 127;
            const float* src = (pa == 0) ? qg : ((pa == 1) ? kg : vg);
            pref = __ldg(src + (t + 1) * D + pi);
        }

        const float* Qs = S.vecs[cur][0];
        const float* Ks = S.vecs[cur][1];
        const float* Vs = S.vecs[cur][2];
        const float4 q4 = reinterpret_cast<const float4*>(Qs)[L];
        const float4 k4 = reinterpret_cast<const float4*>(Ks)[L];
        const float4 v4 = reinterpret_cast<const float4*>(Vs)[L];

        // ---- P-phase: Pqq RMW + u' column partials, Pqv(reg) RMW + sl fold ----
        float4 up = make_float4(0.f, 0.f, 0.f, 0.f);
        float slp = 0.f;
#pragma unroll
        for (int j = 0; j < 8; j++) {
            const int r = w + 16 * j;
            const float qr = Qs[r], kr = Ks[r];

            float4* pqp = reinterpret_cast<float4*>(S.Pqq) + r * 32 + L;
            float4 pq = *pqp;
            // u' from OLD value (Pqq_{t-1} k, by symmetry = column fold)
            up.x = fmaf(kr, pq.x, up.x); up.y = fmaf(kr, pq.y, up.y);
            up.z = fmaf(kr, pq.z, up.z); up.w = fmaf(kr, pq.w, up.w);
            pq.x = fmaf(qr, q4.x, pq.x); pq.y = fmaf(qr, q4.y, pq.y);
            pq.z = fmaf(qr, q4.z, pq.z); pq.w = fmaf(qr, q4.w, pq.w);
            *pqp = pq;

            // Pqv row in registers
            Pv[j].x = fmaf(qr, v4.x, Pv[j].x); Pv[j].y = fmaf(qr, v4.y, Pv[j].y);
            Pv[j].z = fmaf(qr, v4.z, Pv[j].z); Pv[j].w = fmaf(qr, v4.w, Pv[j].w);
            slp = fmaf(kr, dot4(Pv[j], v4), slp);   // k^T Pqv_t v fold
        }
        reinterpret_cast<float4*>(S.upart)[w * 32 + L] = up;
        slp = wred(slp);
        if (L == 0) S.slot_sl[cur][w] = slp;
        __syncthreads();   // bar1: upart + abf(from SC) visible

        // ---- J-phase: deferred J update, w = Jq partials, reduce u' ----
        const float aco = S.abf[0];
        const float bco = S.abf[1];
        const float4 kp4 = reinterpret_cast<const float4*>(S.vecs[nxt][1])[L];
        const float* VPs = S.vecs[nxt][2];
        float jqvp = 0.f;
#pragma unroll
        for (int j = 0; j < 8; j++) {
            const int r = w + 16 * j;
            const float bv = bco * VPs[r];
            float4 Jn;
            Jn.x = fmaf(aco, J[j].x, bv * kp4.x);
            Jn.y = fmaf(aco, J[j].y, bv * kp4.y);
            Jn.z = fmaf(aco, J[j].z, bv * kp4.z);
            Jn.w = fmaf(aco, J[j].w, bv * kp4.w);
            J[j] = Jn;
            const float jq = dot4(Jn, q4);          // lane partial of w_r
            jqvp = fmaf(Vs[r], jq, jqvp);           // v . (J q) fold
            S.wpart[L * WSTRIDE + r] = jq;
        }
        jqvp = wred(jqvp);
        if (L == 0) S.slot_jqv[w] = jqvp;
        if (w == 0) {
            const float qkp = wred(dot4(q4, k4));
            const float vvp = wred(dot4(v4, v4));
            if (L == 0) { S.qk_s = qkp; S.vv_s = vvp; }
        }
        if (tid < D) {   // reduce u' across 16 warps (conflict-free)
            float U = 0.f;
#pragma unroll
            for (int ww = 0; ww < NW; ww++) U += S.upart[ww * D + tid];
            S.u[tid] = U;
            const float kup = wred(Ks[tid] * U);    // k . u'
            if (L == 0) S.slot_ku[w] = kup;
        }
        __syncthreads();   // bar2: u[], wpart visible

        // ---- mu-phase: mu' = v^T J u' ; jq2 = ||Jq||^2 ; prefetch store ----
        {
            const float4 u4 = reinterpret_cast<const float4*>(S.u)[L];
            float mup = 0.f;
#pragma unroll
            for (int j = 0; j < 8; j++) {
                const int r = w + 16 * j;
                mup = fmaf(Vs[r], dot4(J[j], u4), mup);
            }
            mup = wred(mup);
            if (L == 0) S.slot_mu[w] = mup;
        }
        if (tid < D) {
            float wr = 0.f;
#pragma unroll
            for (int LL = 0; LL < 32; LL++) wr += S.wpart[LL * WSTRIDE + tid];
            const float jq2p = wred(wr * wr);
            if (L == 0) S.slot_jq2[w] = jq2p;
        }
        if (doPref) S.vecs[nxt][pa][pi] = pref;
        __syncthreads();   // bar3: slots + next vecs visible
    }

    // ---- epilogue: final scalar phase, apply deferred J update, write J ----
    if (w == 0) scalar_phase(S, T_STEPS - 1, L, T1, T2, Tvv, out);
    __syncthreads();
    {
        const float aco = S.abf[0];
        const float bco = S.abf[1];
        const int cur = (T_STEPS - 1) & 1;
        const float4 kc4 = reinterpret_cast<const float4*>(S.vecs[cur][1])[L];
        const float* Vc = S.vecs[cur][2];
        float4* Jout = reinterpret_cast<float4*>(out + 2 * T_STEPS);
#pragma unroll
        for (int j = 0; j < 8; j++) {
            const int r = w + 16 * j;
            const float bv = bco * Vc[r];
            float4 Jn;
            Jn.x = fmaf(aco, J[j].x, bv * kc4.x);
            Jn.y = fmaf(aco, J[j].y, bv * kc4.y);
            Jn.z = fmaf(aco, J[j].z, bv * kc4.z);
            Jn.w = fmaf(aco, J[j].w, bv * kc4.w);
            Jout[r * 32 + L] = Jn;
        }
    }
}

extern "C" void kernel_launch(void* const* d_in, const int* in_sizes, int n_in,
                              void* d_out, int out_size)
{
    const float* q = (const float*)d_in[0];
    const float* k = (const float*)d_in[1];
    const float* v = (const float*)d_in[2];
    float* out = (float*)d_out;
    (void)in_sizes; (void)n_in; (void)out_size;

    cudaFuncSetAttribute(gim_kernel,
                         cudaFuncAttributeMaxDynamicSharedMemorySize,
                         (int)sizeof(Smem));
    gim_kernel<<<1, NT, sizeof(Smem)>>>(q, k, v, out);
}

// round 8
// speedup vs baseline: 1.7773x; 1.0953x over previous
#include <cuda_runtime.h>
#include <stdint.h>

// GreedyInvasionMemory v3: 512 threads / 16 warps, warp w owns rows {w+16j}.
// f32x2 packed FMA throughout; J + Pqv in registers (as float2 pairs);
// Pqq in smem (one RMW pass/step). Butterfly reduction for w=Jq scalars.
// Warp 0: overlapped scalar phase. Warps 12-15: u/y cross-warp reductions.

#define T_STEPS 2048
#define D 128
#define NT 512
#define NW 16

typedef unsigned long long u64;
struct f2 { u64 v; };

__device__ __forceinline__ f2 mk2(float x, float y) {
    f2 r; asm("mov.b64 %0, {%1, %2};" : "=l"(r.v) : "f"(x), "f"(y)); return r;
}
__device__ __forceinline__ f2 fma2(f2 a, f2 b, f2 c) {
    f2 d; asm("fma.rn.f32x2 %0, %1, %2, %3;" : "=l"(d.v) : "l"(a.v), "l"(b.v), "l"(c.v));
    return d;
}
__device__ __forceinline__ f2 mul2(f2 a, f2 b) {
    f2 d; asm("mul.rn.f32x2 %0, %1, %2;" : "=l"(d.v) : "l"(a.v), "l"(b.v)); return d;
}
__device__ __forceinline__ float sum2(f2 a) {
    float x, y; asm("mov.b64 {%0, %1}, %2;" : "=f"(x), "=f"(y) : "l"(a.v));
    return x + y;
}
__device__ __forceinline__ float wred(float x) {
    x += __shfl_xor_sync(0xffffffffu, x, 16);
    x += __shfl_xor_sync(0xffffffffu, x, 8);
    x += __shfl_xor_sync(0xffffffffu, x, 4);
    x += __shfl_xor_sync(0xffffffffu, x, 2);
    x += __shfl_xor_sync(0xffffffffu, x, 1);
    return x;
}

struct Smem {
    float Pqq[D * D];            // 64 KB, sum q q^T
    float vecs[2][3][D];         // plain q/k/v, double-buffered
    u64   vecs2[2][3][D];        // duplicated-pair q/k/v (for row-scalar broadcasts)
    float upart[NW * D];         // per-warp column partials of u' = Pqq_{t-1} k
    float ypart[NW * D];         // per-warp column partials of y  = J^T v
    float slot_sl[2][NW];
    float slot_jqv[2][NW];
    float slot_jq2[2][NW];
    float slot_ku[2][4];
    float slot_mu[2][4];
    float qkvv[2][2];
    float abf[2];                // (A, B) deferred J-update coefficients
};

// Scalar phase for step t (warp 0, all lanes). Reads parity t&1 slots.
__device__ __forceinline__ void scalar_phase(Smem& S, int t, int L,
                                             double& T1, double& T2, double& Tvv,
                                             float& t1f, float& t2f,
                                             float* __restrict__ out)
{
    const int par = t & 1;
    float a1 = (L < NW) ? S.slot_sl[par][L]  : 0.f;
    float a2 = (L < NW) ? S.slot_jqv[par][L] : 0.f;
    float a3 = (L < NW) ? S.slot_jq2[par][L] : 0.f;
    const float sl  = wred(a1);
    const float jqv = wred(a2);
    const float jq2 = wred(a3);
    if (L == 0) {
        const float kup = S.slot_ku[par][0] + S.slot_ku[par][1]
                        + S.slot_ku[par][2] + S.slot_ku[par][3];
        const float mup = S.slot_mu[par][0] + S.slot_mu[par][1]
                        + S.slot_mu[par][2] + S.slot_mu[par][3];
        const float qk = S.qkvv[par][0];
        const float vv = S.qkvv[par][1];
        const float ku = fmaf(qk, qk, kup);      // k^T Pqq_t k
        const float mu = fmaf(jqv, qk, mup);     // v^T J Pqq_t k

        // fast float decision path (shadows of the double accumulators)
        const float sJs  = t1f + jqv;            // trace(J Pqv_t), sum scale
        const float AJJs_raw = t2f + jq2;        // trace(J Pqq_t J^T), sum scale
        const float fl  = (float)(t + 1);
        const float inv = 1.f / fl;
        const float sJ  = sJs * inv;
        const float AJJ = AJJs_raw * inv;
        const float sl_ = sl * inv;
        const float All = vv * ku * inv;
        const float AJl = mu * inv;
        const bool first = (t == 0);

        const float AJJs = (first || AJJ == 0.f) ? 1.f : AJJ;
        const float Alls = (first || All == 0.f) ? 1.f : All;
        const float denom = AJJ * All - AJl * AJl;
        const float denoms = (first || denom == 0.f) ? 1.f : denom;
        const float rA = 1.f / AJJs;             // independent divides (ILP)
        const float rL = 1.f / Alls;
        const float rD = 1.f / denoms;

        const float margin = sl_ - AJl * (sJ * rA);
        const float wf = (All * sJ - AJl * sl_) * rD;
        const float wi = (AJJ * sl_ - AJl * sJ) * rD;
        const float wfc = (wi <= 0.f) ? (sJ * rA) : ((wf <= 0.f) ? 0.f : wf);
        const float wic = (wi <= 0.f) ? 0.f : ((wf <= 0.f) ? (sl_ * rL) : wi);
        const bool dou = margin > 0.f;

        const float A = first ? 0.f : (dou ? wfc : 1.f);
        const float B = first ? 1.f : (dou ? wic : 0.f);
        S.abf[0] = A; S.abf[1] = B;              // released at next barrier

        // double bookkeeping (off critical path)
        const double T1p = T1 + (double)jqv;
        const double T2p = T2 + (double)jq2;
        Tvv += (double)vv;
        T1 = (double)A * T1p + (double)B * (double)sl;
        T2 = (double)A * (double)A * T2p
           + 2.0 * (double)A * (double)B * (double)mu
           + (double)B * (double)B * (double)ku * (double)vv;
        t1f = (float)T1; t2f = (float)T2;

        out[t]           = (float)(0.5 * Tvv - T1 + 0.5 * T2) * inv;
        out[T_STEPS + t] = (first || dou) ? 1.f : 0.f;
    }
}

extern __shared__ char smem_raw[];

__global__ void __launch_bounds__(NT, 1)
gim_kernel(const float* __restrict__ qg,
           const float* __restrict__ kg,
           const float* __restrict__ vg,
           float* __restrict__ out)
{
    Smem& S = *reinterpret_cast<Smem*>(smem_raw);
    const int tid = threadIdx.x;
    const int w = tid >> 5;     // warp 0..15, rows w+16j
    const int L = tid & 31;     // lane: cols 4L..4L+3

    // ---- init ----
    {
        float4 z4 = make_float4(0.f, 0.f, 0.f, 0.f);
        for (int i = tid; i < D * D / 4; i += NT)
            reinterpret_cast<float4*>(S.Pqq)[i] = z4;
    }
    if (tid < 3 * D) {
        const int a = tid >> 7, i = tid & 127;
        const float* src = (a == 0) ? qg : ((a == 1) ? kg : vg);
        const float val = src[i];
        S.vecs[0][a][i] = val;  S.vecs2[0][a][i] = mk2(val, val).v;
        S.vecs[1][a][i] = 0.f;  S.vecs2[1][a][i] = 0ull;
    }
    if (tid == 0) { S.abf[0] = 1.f; S.abf[1] = 0.f; }

    f2 Jlo[8], Jhi[8], Pvlo[8], Pvhi[8];
#pragma unroll
    for (int j = 0; j < 8; j++) {
        Jlo[j].v = 0ull; Jhi[j].v = 0ull; Pvlo[j].v = 0ull; Pvhi[j].v = 0ull;
    }
    double T1 = 0.0, T2 = 0.0, Tvv = 0.0;
    float t1f = 0.f, t2f = 0.f;
    float Ukeep = 0.f;   // warps 12-15: u'_c carried phase2 -> phase3

    __syncthreads();

    for (int t = 0; t < T_STEPS; ++t) {
        const int cur = t & 1, nxt = cur ^ 1, par = t & 1;

        // ---- scalar phase for step t-1 (warp 0), overlapped with phase 1 ----
        if (t > 0 && w == 0) scalar_phase(S, t - 1, L, T1, T2, Tvv, t1f, t2f, out);

        // prefetch next step's vectors (threads 128..511 cover 3*128 elements)
        float pref = 0.f; int pa = 0, pi = 0;
        const bool doPref = (tid >= 128) && (t + 1 < T_STEPS);
        if (doPref) {
            const int idx = tid - 128;
            pa = idx >> 7; pi = idx & 127;
            const float* src = (pa == 0) ? qg : ((pa == 1) ? kg : vg);
            pref = __ldg(src + (t + 1) * D + pi);
        }

        // current-step vectors as f2 pairs
        const ulonglong2 qp = reinterpret_cast<const ulonglong2*>(S.vecs[cur][0])[L];
        const ulonglong2 kp = reinterpret_cast<const ulonglong2*>(S.vecs[cur][1])[L];
        const ulonglong2 vp = reinterpret_cast<const ulonglong2*>(S.vecs[cur][2])[L];
        const f2 qlo{qp.x}, qhi{qp.y}, klo{kp.x}, khi{kp.y}, vlo{vp.x}, vhi{vp.y};

        // ---- phase 1: Pqq RMW + u' col partials; Pqv(reg) upd + sl fold ----
        f2 uplo; uplo.v = 0ull; f2 uphi; uphi.v = 0ull;
        f2 slp2; slp2.v = 0ull;
#pragma unroll
        for (int j = 0; j < 8; j++) {
            const int r = w + 16 * j;
            const f2 q2r{S.vecs2[cur][0][r]};
            const f2 k2r{S.vecs2[cur][1][r]};

            ulonglong2* pqp = reinterpret_cast<ulonglong2*>(&S.Pqq[r * D]) + L;
            ulonglong2 pqv_ = *pqp;
            f2 plo{pqv_.x}, phi{pqv_.y};
            uplo = fma2(k2r, plo, uplo);          // u' fold on OLD value
            uphi = fma2(k2r, phi, uphi);
            plo = fma2(q2r, qlo, plo);            // Pqq += q q^T
            phi = fma2(q2r, qhi, phi);
            *pqp = make_ulonglong2(plo.v, phi.v);

            Pvlo[j] = fma2(q2r, vlo, Pvlo[j]);    // Pqv += q v^T
            Pvhi[j] = fma2(q2r, vhi, Pvhi[j]);
            const f2 d2 = fma2(Pvhi[j], vhi, mul2(Pvlo[j], vlo));
            slp2 = fma2(k2r, d2, slp2);           // sl = k^T Pqv_t v fold
        }
        reinterpret_cast<ulonglong2*>(&S.upart[w * D])[L] =
            make_ulonglong2(uplo.v, uphi.v);
        {
            const float slp = wred(sum2(slp2));
            if (L == 0) S.slot_sl[par][w] = slp;
        }
        if (w == 1) {
            const float qkp = wred(sum2(fma2(qhi, khi, mul2(qlo, klo))));
            const float vvp = wred(sum2(fma2(vhi, vhi, mul2(vlo, vlo))));
            if (L == 0) { S.qkvv[par][0] = qkp; S.qkvv[par][1] = vvp; }
        }
        __syncthreads();   // bar1: upart, slots, abf(from SC) visible

        // ---- phase 2: J update + y fold + w=Jq (butterfly); u' reduce ----
        {
            const float af = S.abf[0], bf = S.abf[1];
            const f2 A2 = mk2(af, af), B2 = mk2(bf, bf);
            const ulonglong2 kpp =
                reinterpret_cast<const ulonglong2*>(S.vecs[nxt][1])[L]; // k_{t-1}
            const f2 kplo{kpp.x}, kphi{kpp.y};
            f2 ylo; ylo.v = 0ull; f2 yhi; yhi.v = 0ull;
            f2 zero2; zero2.v = 0ull;
            float p[8];
#pragma unroll
            for (int j = 0; j < 8; j++) {
                const int r = w + 16 * j;
                const f2 vp2{S.vecs2[nxt][2][r]};   // v_{t-1}[r]
                const f2 v2r{S.vecs2[cur][2][r]};   // v_t[r]
                const f2 bv2 = mul2(B2, vp2);
                Jlo[j] = fma2(A2, Jlo[j], mul2(bv2, kplo));
                Jhi[j] = fma2(A2, Jhi[j], mul2(bv2, kphi));
                ylo = fma2(v2r, Jlo[j], ylo);       // y = J^T v col partials
                yhi = fma2(v2r, Jhi[j], yhi);
                const f2 wd = fma2(Jlo[j], qlo, fma2(Jhi[j], qhi, zero2));
                p[j] = sum2(wd);                     // lane partial of w_r
            }
            reinterpret_cast<ulonglong2*>(&S.ypart[w * D])[L] =
                make_ulonglong2(ylo.v, yhi.v);

            // butterfly: 8 row-partials x 32 lanes -> lane L holds w_{w+16*(L&7)}
            float bb[4];
#pragma unroll
            for (int m = 0; m < 4; m++) {
                const float send = (L & 1) ? p[2 * m] : p[2 * m + 1];
                const float recv = __shfl_xor_sync(0xffffffffu, send, 1);
                bb[m] = ((L & 1) ? p[2 * m + 1] : p[2 * m]) + recv;
            }
            float cc[2];
#pragma unroll
            for (int m = 0; m < 2; m++) {
                const float send = (L & 2) ? bb[2 * m] : bb[2 * m + 1];
                const float recv = __shfl_xor_sync(0xffffffffu, send, 2);
                cc[m] = ((L & 2) ? bb[2 * m + 1] : bb[2 * m]) + recv;
            }
            {
                const float send = (L & 4) ? cc[0] : cc[1];
                const float recv = __shfl_xor_sync(0xffffffffu, send, 4);
                float wv = ((L & 4) ? cc[1] : cc[0]) + recv;
                wv += __shfl_xor_sync(0xffffffffu, wv, 8);
                wv += __shfl_xor_sync(0xffffffffu, wv, 16);
                const float vrow = S.vecs[cur][2][w + 16 * (L & 7)];
                float f = vrow * wv, g = wv * wv;
                f += __shfl_xor_sync(0xffffffffu, f, 1);
                f += __shfl_xor_sync(0xffffffffu, f, 2);
                f += __shfl_xor_sync(0xffffffffu, f, 4);
                g += __shfl_xor_sync(0xffffffffu, g, 1);
                g += __shfl_xor_sync(0xffffffffu, g, 2);
                g += __shfl_xor_sync(0xffffffffu, g, 4);
                if (L == 0) { S.slot_jqv[par][w] = f; S.slot_jq2[par][w] = g; }
            }
        }
        if (w >= 12) {   // u' cross-warp reduce + ku fold (keep U for phase 3)
            const int c = tid - 384;
            float U = 0.f;
#pragma unroll
            for (int ww = 0; ww < NW; ww++) U += S.upart[ww * D + c];
            Ukeep = U;
            const float kuP = wred(S.vecs[cur][1][c] * U);
            if (L == 0) S.slot_ku[par][w - 12] = kuP;
        }
        __syncthreads();   // bar2: ypart + ku slots visible

        // ---- phase 3: y reduce + mu = u'.y ; prefetch store ----
        if (w >= 12) {
            const int c = tid - 384;
            float Y = 0.f;
#pragma unroll
            for (int ww = 0; ww < NW; ww++) Y += S.ypart[ww * D + c];
            const float muP = wred(Ukeep * Y);
            if (L == 0) S.slot_mu[par][w - 12] = muP;
        }
        if (doPref) {
            S.vecs[nxt][pa][pi] = pref;
            S.vecs2[nxt][pa][pi] = mk2(pref, pref).v;
        }
        __syncthreads();   // bar3: slots + next-step vecs visible
    }

    // ---- epilogue: final scalar phase, apply deferred J update, write J ----
    if (w == 0) scalar_phase(S, T_STEPS - 1, L, T1, T2, Tvv, t1f, t2f, out);
    __syncthreads();
    {
        const float af = S.abf[0], bf = S.abf[1];
        const f2 A2 = mk2(af, af), B2 = mk2(bf, bf);
        const int fcur = (T_STEPS - 1) & 1;
        const ulonglong2 kpp =
            reinterpret_cast<const ulonglong2*>(S.vecs[fcur][1])[L];
        const f2 kplo{kpp.x}, kphi{kpp.y};
#pragma unroll
        for (int j = 0; j < 8; j++) {
            const int r = w + 16 * j;
            const f2 vp2{S.vecs2[fcur][2][r]};
            const f2 bv2 = mul2(B2, vp2);
            const f2 jl = fma2(A2, Jlo[j], mul2(bv2, kplo));
            const f2 jh = fma2(A2, Jhi[j], mul2(bv2, kphi));
            reinterpret_cast<ulonglong2*>(out + 2 * T_STEPS + r * D)[L] =
                make_ulonglong2(jl.v, jh.v);
        }
    }
}

extern "C" void kernel_launch(void* const* d_in, const int* in_sizes, int n_in,
                              void* d_out, int out_size)
{
    const float* q = (const float*)d_in[0];
    const float* k = (const float*)d_in[1];
    const float* v = (const float*)d_in[2];
    float* out = (float*)d_out;
    (void)in_sizes; (void)n_in; (void)out_size;

    cudaFuncSetAttribute(gim_kernel,
                         cudaFuncAttributeMaxDynamicSharedMemorySize,
                         (int)sizeof(Smem));
    gim_kernel<<<1, NT, sizeof(Smem)>>>(q, k, v, out);
}